// round 1
// baseline (speedup 1.0000x reference)
#include <cuda_runtime.h>
#include <cuda_bf16.h>
#include <math.h>

#define N_TOK  2048
#define DIMM   1024
#define NBATCH 2
#define NHEAD  16
#define DHEAD  64
#define BETA_V 0.125f

// Scratch (static device allocation — allowed; no cudaMalloc anywhere)
__device__ float g_qk[(size_t)(NBATCH * N_TOK) * (2 * DIMM)];  // 32 MB: [4096, 2048]
__device__ float g_ao[(size_t)(NBATCH * N_TOK) * DIMM];        // 16 MB: [4096, 1024]

// ---------------------------------------------------------------------------
// SGEMM: C[M,N] = A[M,K] @ B[K,N], row-major. 128x128 block, BK=8, 8x8/thread.
// M,N multiples of 128; K multiple of 8 (true for all three calls).
// ---------------------------------------------------------------------------
__global__ void __launch_bounds__(256) sgemm_kernel(
    const float* __restrict__ A, const float* __restrict__ B,
    float* __restrict__ C, int M, int N, int K)
{
    __shared__ float As[8][128];   // transposed A tile: As[k][m]
    __shared__ float Bs[8][128];   // Bs[k][n]

    const int tx   = threadIdx.x;
    const int brow = blockIdx.y, bcol = blockIdx.x;
    const int trow = tx >> 4, tcol = tx & 15;       // 16x16 thread grid
    const int aRow = tx >> 1, aCol = (tx & 1) * 4;  // A tile loader mapping
    const int bRow = tx >> 5, bCol = (tx & 31) * 4; // B tile loader mapping

    const float* Ap = A + (size_t)(brow * 128 + aRow) * K + aCol;
    const float* Bp = B + (size_t)bRow * N + bcol * 128 + bCol;

    float acc[8][8];
#pragma unroll
    for (int i = 0; i < 8; i++)
#pragma unroll
        for (int j = 0; j < 8; j++) acc[i][j] = 0.f;

    for (int k0 = 0; k0 < K; k0 += 8) {
        float4 av = *(const float4*)(Ap + k0);
        As[aCol + 0][aRow] = av.x;
        As[aCol + 1][aRow] = av.y;
        As[aCol + 2][aRow] = av.z;
        As[aCol + 3][aRow] = av.w;
        *(float4*)&Bs[bRow][bCol] = *(const float4*)(Bp + (size_t)k0 * N);
        __syncthreads();

#pragma unroll
        for (int kk = 0; kk < 8; kk++) {
            float4 a0 = *(const float4*)&As[kk][trow * 8];
            float4 a1 = *(const float4*)&As[kk][trow * 8 + 4];
            float4 b0 = *(const float4*)&Bs[kk][tcol * 8];
            float4 b1 = *(const float4*)&Bs[kk][tcol * 8 + 4];
            float ar[8] = {a0.x, a0.y, a0.z, a0.w, a1.x, a1.y, a1.z, a1.w};
            float br[8] = {b0.x, b0.y, b0.z, b0.w, b1.x, b1.y, b1.z, b1.w};
#pragma unroll
            for (int i = 0; i < 8; i++)
#pragma unroll
                for (int j = 0; j < 8; j++)
                    acc[i][j] += ar[i] * br[j];
        }
        __syncthreads();
    }

#pragma unroll
    for (int i = 0; i < 8; i++) {
        float* Cp = C + (size_t)(brow * 128 + trow * 8 + i) * N + bcol * 128 + tcol * 8;
        *(float4*)(Cp)     = make_float4(acc[i][0], acc[i][1], acc[i][2], acc[i][3]);
        *(float4*)(Cp + 4) = make_float4(acc[i][4], acc[i][5], acc[i][6], acc[i][7]);
    }
}

// ---------------------------------------------------------------------------
// Causal flash attention. qk = [b*n, 2048]: q at col h*64, k at col 1024+h*64.
// K reused as V. Grid (n/64, heads, batch), 256 threads.
// Thread mapping: row = tid/4 (query row in tile), cg = tid%4 (col/key group).
// Keys interleaved per thread: j = 4*jj + cg  (bank-conflict-free S compute).
// ---------------------------------------------------------------------------
__global__ void __launch_bounds__(256) attn_kernel(
    const float* __restrict__ qk, float* __restrict__ out)
{
    const int qt = blockIdx.x, h = blockIdx.y, bb = blockIdx.z;
    const int tid = threadIdx.x;
    const int row = tid >> 2;   // 0..63
    const int cg  = tid & 3;    // 0..3

    __shared__ float Ks[64][68];
    __shared__ float Ps[64][68];

    const int qrow_g = bb * N_TOK + qt * 64 + row;
    const float* qptr = qk + (size_t)qrow_g * (2 * DIMM) + h * DHEAD;

    // Cache this thread's q row (pre-scaled by beta) in registers.
    float4 qreg[16];
#pragma unroll
    for (int i = 0; i < 16; i++) {
        float4 v = *(const float4*)(qptr + i * 4);
        v.x *= BETA_V; v.y *= BETA_V; v.z *= BETA_V; v.w *= BETA_V;
        qreg[i] = v;
    }

    float acc[16];
#pragma unroll
    for (int i = 0; i < 16; i++) acc[i] = 0.f;
    float mrow = -1e30f, lrow = 0.f;

    for (int kt = 0; kt <= qt; kt++) {
        // Load K tile [64 keys, 64 dims] into SMEM (also serves as V).
#pragma unroll
        for (int i = tid; i < 64 * 16; i += 256) {
            int r = i >> 4, c = (i & 15) * 4;
            const float* kp = qk + (size_t)(bb * N_TOK + kt * 64 + r) * (2 * DIMM)
                              + DIMM + h * DHEAD + c;
            *(float4*)&Ks[r][c] = *(const float4*)kp;
        }
        __syncthreads();

        // Scores for this thread's 16 keys: j = 4*jj + cg
        float s[16];
#pragma unroll
        for (int jj = 0; jj < 16; jj++) {
            const float4* kr = (const float4*)&Ks[jj * 4 + cg][0];
            float sum = 0.f;
#pragma unroll
            for (int d = 0; d < 16; d++) {
                float4 k4 = kr[d];
                float4 q4 = qreg[d];
                sum += q4.x * k4.x;
                sum += q4.y * k4.y;
                sum += q4.z * k4.z;
                sum += q4.w * k4.w;
            }
            s[jj] = sum;
        }

        // Causal mask (diagonal tile only; off-diagonal tiles fully valid).
        if (kt == qt) {
#pragma unroll
            for (int jj = 0; jj < 16; jj++)
                if (jj * 4 + cg > row) s[jj] = -1e30f;
        }

        // Online softmax: row max across 4 lanes sharing this row.
        float tmax = s[0];
#pragma unroll
        for (int jj = 1; jj < 16; jj++) tmax = fmaxf(tmax, s[jj]);
        tmax = fmaxf(tmax, __shfl_xor_sync(0xffffffffu, tmax, 1));
        tmax = fmaxf(tmax, __shfl_xor_sync(0xffffffffu, tmax, 2));
        float mnew = fmaxf(mrow, tmax);
        float corr = __expf(mrow - mnew);

        float lsum = 0.f;
#pragma unroll
        for (int jj = 0; jj < 16; jj++) {
            float p = __expf(s[jj] - mnew);
            s[jj] = p;
            lsum += p;
        }
        lsum += __shfl_xor_sync(0xffffffffu, lsum, 1);
        lsum += __shfl_xor_sync(0xffffffffu, lsum, 2);
        lrow = lrow * corr + lsum;
        mrow = mnew;
#pragma unroll
        for (int d = 0; d < 16; d++) acc[d] *= corr;

        // Stage P in SMEM (scattered by interleave; conflict-free scalar STS).
#pragma unroll
        for (int jj = 0; jj < 16; jj++) Ps[row][jj * 4 + cg] = s[jj];
        __syncwarp();

        // acc += P @ V  (V = K tile). This thread owns d-cols [cg*16, cg*16+16).
#pragma unroll
        for (int j4 = 0; j4 < 16; j4++) {
            float4 p4 = *(const float4*)&Ps[row][j4 * 4];
            float pv[4] = {p4.x, p4.y, p4.z, p4.w};
#pragma unroll
            for (int u = 0; u < 4; u++) {
                float p = pv[u];
                const float4* vr = (const float4*)&Ks[j4 * 4 + u][cg * 16];
                float4 v0 = vr[0], v1 = vr[1], v2 = vr[2], v3 = vr[3];
                acc[0]  += p * v0.x; acc[1]  += p * v0.y; acc[2]  += p * v0.z; acc[3]  += p * v0.w;
                acc[4]  += p * v1.x; acc[5]  += p * v1.y; acc[6]  += p * v1.z; acc[7]  += p * v1.w;
                acc[8]  += p * v2.x; acc[9]  += p * v2.y; acc[10] += p * v2.z; acc[11] += p * v2.w;
                acc[12] += p * v3.x; acc[13] += p * v3.y; acc[14] += p * v3.z; acc[15] += p * v3.w;
            }
        }
        __syncthreads();
    }

    // Epilogue: normalize and write [b, n, h*d] so out-proj is a plain GEMM.
    float inv = 1.f / lrow;
    float* op = out + (size_t)qrow_g * DIMM + h * DHEAD + cg * 16;
#pragma unroll
    for (int d = 0; d < 16; d += 4)
        *(float4*)(op + d) = make_float4(acc[d] * inv, acc[d + 1] * inv,
                                         acc[d + 2] * inv, acc[d + 3] * inv);
}

// ---------------------------------------------------------------------------
extern "C" void kernel_launch(void* const* d_in, const int* in_sizes, int n_in,
                              void* d_out, int out_size)
{
    const float* x     = (const float*)d_in[0];
    const float* W_qk  = (const float*)d_in[1];
    const float* W_out = (const float*)d_in[2];
    float* out = (float*)d_out;

    float *qkbuf = nullptr, *aobuf = nullptr;
    cudaGetSymbolAddress((void**)&qkbuf, g_qk);
    cudaGetSymbolAddress((void**)&aobuf, g_ao);

    dim3 t(256);
    // qk = x @ W_qk : [4096,1024]@[1024,2048]
    sgemm_kernel<<<dim3((2 * DIMM) / 128, (NBATCH * N_TOK) / 128), t>>>(
        x, W_qk, qkbuf, NBATCH * N_TOK, 2 * DIMM, DIMM);
    // causal attention, K reused as V
    attn_kernel<<<dim3(N_TOK / 64, NHEAD, NBATCH), t>>>(qkbuf, aobuf);
    // out = ao @ W_out : [4096,1024]@[1024,1024]
    sgemm_kernel<<<dim3(DIMM / 128, (NBATCH * N_TOK) / 128), t>>>(
        aobuf, W_out, out, NBATCH * N_TOK, DIMM, DIMM);
}

// round 2
// speedup vs baseline: 2.7793x; 2.7793x over previous
#include <cuda_runtime.h>
#include <cuda_bf16.h>
#include <math.h>

#define N_TOK  2048
#define DIMM   1024
#define NBATCH 2
#define NHEAD  16
#define DHEAD  64
#define BETA_V 0.125f

// Scratch (static device allocation — allowed; no cudaMalloc anywhere)
__device__ float g_qk[(size_t)(NBATCH * N_TOK) * (2 * DIMM)];  // 32 MB: [4096, 2048]
__device__ float g_ao[(size_t)(NBATCH * N_TOK) * DIMM];        // 16 MB: [4096, 1024]

// ---------------------------------------------------------------------------
// SGEMM: C[M,N] = A[M,K] @ B[K,N], row-major. 128x128 block, BK=8, 8x8/thread.
// (unchanged from R1 — known good; will be tensorized next round)
// ---------------------------------------------------------------------------
__global__ void __launch_bounds__(256) sgemm_kernel(
    const float* __restrict__ A, const float* __restrict__ B,
    float* __restrict__ C, int M, int N, int K)
{
    __shared__ float As[8][128];
    __shared__ float Bs[8][128];

    const int tx   = threadIdx.x;
    const int brow = blockIdx.y, bcol = blockIdx.x;
    const int trow = tx >> 4, tcol = tx & 15;
    const int aRow = tx >> 1, aCol = (tx & 1) * 4;
    const int bRow = tx >> 5, bCol = (tx & 31) * 4;

    const float* Ap = A + (size_t)(brow * 128 + aRow) * K + aCol;
    const float* Bp = B + (size_t)bRow * N + bcol * 128 + bCol;

    float acc[8][8];
#pragma unroll
    for (int i = 0; i < 8; i++)
#pragma unroll
        for (int j = 0; j < 8; j++) acc[i][j] = 0.f;

    for (int k0 = 0; k0 < K; k0 += 8) {
        float4 av = *(const float4*)(Ap + k0);
        As[aCol + 0][aRow] = av.x;
        As[aCol + 1][aRow] = av.y;
        As[aCol + 2][aRow] = av.z;
        As[aCol + 3][aRow] = av.w;
        *(float4*)&Bs[bRow][bCol] = *(const float4*)(Bp + (size_t)k0 * N);
        __syncthreads();

#pragma unroll
        for (int kk = 0; kk < 8; kk++) {
            float4 a0 = *(const float4*)&As[kk][trow * 8];
            float4 a1 = *(const float4*)&As[kk][trow * 8 + 4];
            float4 b0 = *(const float4*)&Bs[kk][tcol * 8];
            float4 b1 = *(const float4*)&Bs[kk][tcol * 8 + 4];
            float ar[8] = {a0.x, a0.y, a0.z, a0.w, a1.x, a1.y, a1.z, a1.w};
            float br[8] = {b0.x, b0.y, b0.z, b0.w, b1.x, b1.y, b1.z, b1.w};
#pragma unroll
            for (int i = 0; i < 8; i++)
#pragma unroll
                for (int j = 0; j < 8; j++)
                    acc[i][j] += ar[i] * br[j];
        }
        __syncthreads();
    }

#pragma unroll
    for (int i = 0; i < 8; i++) {
        float* Cp = C + (size_t)(brow * 128 + trow * 8 + i) * N + bcol * 128 + tcol * 8;
        *(float4*)(Cp)     = make_float4(acc[i][0], acc[i][1], acc[i][2], acc[i][3]);
        *(float4*)(Cp + 4) = make_float4(acc[i][4], acc[i][5], acc[i][6], acc[i][7]);
    }
}

// ---------------------------------------------------------------------------
// tf32 tensor-core helpers (mma.sync m16n8k8, Ampere-layout, runs on sm_103a)
// ---------------------------------------------------------------------------
__device__ __forceinline__ unsigned f2tf32(float x) {
    unsigned u;
    asm("cvt.rna.tf32.f32 %0, %1;" : "=r"(u) : "f"(x));
    return u;
}

__device__ __forceinline__ void mma_tf32(
    float& c0, float& c1, float& c2, float& c3,
    unsigned a0, unsigned a1, unsigned a2, unsigned a3,
    unsigned b0, unsigned b1)
{
    asm volatile(
        "mma.sync.aligned.m16n8k8.row.col.f32.tf32.tf32.f32 "
        "{%0,%1,%2,%3}, {%4,%5,%6,%7}, {%8,%9}, {%0,%1,%2,%3};"
        : "+f"(c0), "+f"(c1), "+f"(c2), "+f"(c3)
        : "r"(a0), "r"(a1), "r"(a2), "r"(a3), "r"(b0), "r"(b1));
}

// ---------------------------------------------------------------------------
// Tensor-core causal flash attention.
// Block = 128 threads (4 warps), 64 q-rows per block; warp w owns rows
// [w*16, w*16+16) -> softmax stats never cross warps (4-lane shfl groups).
// qk layout: [b*n, 2048], q at col h*64, k at col 1024+h*64. K reused as V.
// ---------------------------------------------------------------------------
__global__ void __launch_bounds__(128) attn_tc_kernel(
    const float* __restrict__ qk, float* __restrict__ out)
{
    const int qt = blockIdx.x, h = blockIdx.y, bb = blockIdx.z;
    const int tid  = threadIdx.x;
    const int w    = tid >> 5;
    const int lane = tid & 31;
    const int g    = lane >> 2;   // 0..7  (row group)
    const int t    = lane & 3;    // 0..3  (thread-in-group)

    __shared__ float Ks[64][68];  // stride 68: S-stage B-frag LDS conflict-free

    // ---- Q fragments: 16 rows x 64 dims, tf32, beta-scaled, in registers ----
    const int qrow0 = bb * N_TOK + qt * 64 + w * 16;
    unsigned qf[8][4];
#pragma unroll
    for (int kc = 0; kc < 8; kc++) {
        const float* qp  = qk + (size_t)(qrow0 + g) * (2 * DIMM) + h * DHEAD + kc * 8;
        const float* qp8 = qp + (size_t)8 * (2 * DIMM);
        qf[kc][0] = f2tf32(qp[t]      * BETA_V);   // (g,   t)
        qf[kc][1] = f2tf32(qp8[t]     * BETA_V);   // (g+8, t)
        qf[kc][2] = f2tf32(qp[t + 4]  * BETA_V);   // (g,   t+4)
        qf[kc][3] = f2tf32(qp8[t + 4] * BETA_V);   // (g+8, t+4)
    }

    float o[8][4];
#pragma unroll
    for (int nt = 0; nt < 8; nt++)
#pragma unroll
        for (int j = 0; j < 4; j++) o[nt][j] = 0.f;
    float m0 = -1e30f, m1 = -1e30f, l0 = 0.f, l1 = 0.f;

    for (int kt = 0; kt <= qt; kt++) {
        // ---- fill K tile (tf32-rounded once here) ----
#pragma unroll
        for (int i = tid; i < 64 * 16; i += 128) {
            int r = i >> 4, c = (i & 15) * 4;
            const float4 v = *(const float4*)(
                qk + (size_t)(bb * N_TOK + kt * 64 + r) * (2 * DIMM)
                   + DIMM + h * DHEAD + c);
            float4 o4;
            o4.x = __uint_as_float(f2tf32(v.x));
            o4.y = __uint_as_float(f2tf32(v.y));
            o4.z = __uint_as_float(f2tf32(v.z));
            o4.w = __uint_as_float(f2tf32(v.w));
            *(float4*)&Ks[r][c] = o4;
        }
        __syncthreads();

        // ---- S = Q @ K^T  (16 x 64 per warp) ----
        float sc[8][4];
#pragma unroll
        for (int nt = 0; nt < 8; nt++) {
            sc[nt][0] = sc[nt][1] = sc[nt][2] = sc[nt][3] = 0.f;
#pragma unroll
            for (int kc = 0; kc < 8; kc++) {
                unsigned b0 = __float_as_uint(Ks[nt * 8 + g][kc * 8 + t]);
                unsigned b1 = __float_as_uint(Ks[nt * 8 + g][kc * 8 + t + 4]);
                mma_tf32(sc[nt][0], sc[nt][1], sc[nt][2], sc[nt][3],
                         qf[kc][0], qf[kc][1], qf[kc][2], qf[kc][3], b0, b1);
            }
        }

        // ---- causal mask (diagonal tile only) ----
        if (kt == qt) {
            const int r0 = w * 16 + g, r1 = r0 + 8;
#pragma unroll
            for (int nt = 0; nt < 8; nt++) {
                int col = nt * 8 + 2 * t;
                if (col     > r0) sc[nt][0] = -1e30f;
                if (col + 1 > r0) sc[nt][1] = -1e30f;
                if (col     > r1) sc[nt][2] = -1e30f;
                if (col + 1 > r1) sc[nt][3] = -1e30f;
            }
        }

        // ---- online softmax (rows g and g+8; reduce over 4-lane group) ----
        float tmax0 = -1e30f, tmax1 = -1e30f;
#pragma unroll
        for (int nt = 0; nt < 8; nt++) {
            tmax0 = fmaxf(tmax0, fmaxf(sc[nt][0], sc[nt][1]));
            tmax1 = fmaxf(tmax1, fmaxf(sc[nt][2], sc[nt][3]));
        }
        tmax0 = fmaxf(tmax0, __shfl_xor_sync(0xffffffffu, tmax0, 1));
        tmax0 = fmaxf(tmax0, __shfl_xor_sync(0xffffffffu, tmax0, 2));
        tmax1 = fmaxf(tmax1, __shfl_xor_sync(0xffffffffu, tmax1, 1));
        tmax1 = fmaxf(tmax1, __shfl_xor_sync(0xffffffffu, tmax1, 2));

        float mn0 = fmaxf(m0, tmax0), mn1 = fmaxf(m1, tmax1);
        float corr0 = __expf(m0 - mn0), corr1 = __expf(m1 - mn1);
        m0 = mn0; m1 = mn1;

        float ls0 = 0.f, ls1 = 0.f;
        unsigned pu[8][4];
#pragma unroll
        for (int nt = 0; nt < 8; nt++) {
            float p0 = __expf(sc[nt][0] - mn0);
            float p1 = __expf(sc[nt][1] - mn0);
            float p2 = __expf(sc[nt][2] - mn1);
            float p3 = __expf(sc[nt][3] - mn1);
            ls0 += p0 + p1;
            ls1 += p2 + p3;
            pu[nt][0] = f2tf32(p0);
            pu[nt][1] = f2tf32(p1);
            pu[nt][2] = f2tf32(p2);
            pu[nt][3] = f2tf32(p3);
        }
        ls0 += __shfl_xor_sync(0xffffffffu, ls0, 1);
        ls0 += __shfl_xor_sync(0xffffffffu, ls0, 2);
        ls1 += __shfl_xor_sync(0xffffffffu, ls1, 1);
        ls1 += __shfl_xor_sync(0xffffffffu, ls1, 2);
        l0 = l0 * corr0 + ls0;
        l1 = l1 * corr1 + ls1;

#pragma unroll
        for (int nt = 0; nt < 8; nt++) {
            o[nt][0] *= corr0; o[nt][1] *= corr0;
            o[nt][2] *= corr1; o[nt][3] *= corr1;
        }

        // ---- O += P @ V  (V = K tile) ----
        // P is in C-frag layout; build A-frags via intra-group shuffles:
        // value (g, c) of an 8-col chunk lives in lane 4g + (c>>1), reg (c&1).
#pragma unroll
        for (int kc = 0; kc < 8; kc++) {
            int src0 = (lane & 28) | (t >> 1);
            int src1 = src0 + 2;
            unsigned v00 = __shfl_sync(0xffffffffu, pu[kc][0], src0);
            unsigned v01 = __shfl_sync(0xffffffffu, pu[kc][1], src0);
            unsigned v10 = __shfl_sync(0xffffffffu, pu[kc][2], src0);
            unsigned v11 = __shfl_sync(0xffffffffu, pu[kc][3], src0);
            unsigned v20 = __shfl_sync(0xffffffffu, pu[kc][0], src1);
            unsigned v21 = __shfl_sync(0xffffffffu, pu[kc][1], src1);
            unsigned v30 = __shfl_sync(0xffffffffu, pu[kc][2], src1);
            unsigned v31 = __shfl_sync(0xffffffffu, pu[kc][3], src1);
            bool odd = (t & 1);
            unsigned a0 = odd ? v01 : v00;   // (g,   kc*8 + t)
            unsigned a1 = odd ? v11 : v10;   // (g+8, kc*8 + t)
            unsigned a2 = odd ? v21 : v20;   // (g,   kc*8 + t+4)
            unsigned a3 = odd ? v31 : v30;   // (g+8, kc*8 + t+4)

#pragma unroll
            for (int nt = 0; nt < 8; nt++) {
                unsigned b0 = __float_as_uint(Ks[kc * 8 + t][nt * 8 + g]);
                unsigned b1 = __float_as_uint(Ks[kc * 8 + t + 4][nt * 8 + g]);
                mma_tf32(o[nt][0], o[nt][1], o[nt][2], o[nt][3],
                         a0, a1, a2, a3, b0, b1);
            }
        }
        __syncthreads();
    }

    // ---- epilogue: normalize, write [b, n, h*d] (plain GEMM layout) ----
    const float inv0 = 1.f / l0, inv1 = 1.f / l1;
    float* op0 = out + (size_t)(qrow0 + g) * DIMM + h * DHEAD;
    float* op1 = op0 + (size_t)8 * DIMM;
#pragma unroll
    for (int nt = 0; nt < 8; nt++) {
        *(float2*)(op0 + nt * 8 + 2 * t) =
            make_float2(o[nt][0] * inv0, o[nt][1] * inv0);
        *(float2*)(op1 + nt * 8 + 2 * t) =
            make_float2(o[nt][2] * inv1, o[nt][3] * inv1);
    }
}

// ---------------------------------------------------------------------------
extern "C" void kernel_launch(void* const* d_in, const int* in_sizes, int n_in,
                              void* d_out, int out_size)
{
    const float* x     = (const float*)d_in[0];
    const float* W_qk  = (const float*)d_in[1];
    const float* W_out = (const float*)d_in[2];
    float* out = (float*)d_out;

    float *qkbuf = nullptr, *aobuf = nullptr;
    cudaGetSymbolAddress((void**)&qkbuf, g_qk);
    cudaGetSymbolAddress((void**)&aobuf, g_ao);

    // qk = x @ W_qk : [4096,1024]@[1024,2048]
    sgemm_kernel<<<dim3((2 * DIMM) / 128, (NBATCH * N_TOK) / 128), 256>>>(
        x, W_qk, qkbuf, NBATCH * N_TOK, 2 * DIMM, DIMM);
    // causal attention (tf32 tensor cores), K reused as V
    attn_tc_kernel<<<dim3(N_TOK / 64, NHEAD, NBATCH), 128>>>(qkbuf, aobuf);
    // out = ao @ W_out : [4096,1024]@[1024,1024]
    sgemm_kernel<<<dim3(DIMM / 128, (NBATCH * N_TOK) / 128), 256>>>(
        aobuf, W_out, out, NBATCH * N_TOK, DIMM, DIMM);
}

// round 3
// speedup vs baseline: 6.1969x; 2.2296x over previous
#include <cuda_runtime.h>
#include <cuda_bf16.h>
#include <math.h>

#define N_TOK  2048
#define DIMM   1024
#define NBATCH 2
#define NHEAD  16
#define DHEAD  64
#define BETA_V 0.125f

// Scratch (static device allocation — allowed; no cudaMalloc anywhere)
__device__ float g_qk[(size_t)(NBATCH * N_TOK) * (2 * DIMM)];  // 32 MB: [4096, 2048]
__device__ float g_ao[(size_t)(NBATCH * N_TOK) * DIMM];        // 16 MB: [4096, 1024]

// ---------------------------------------------------------------------------
// tf32 tensor-core helpers (mma.sync m16n8k8, Ampere layout, valid on sm_103a)
// ---------------------------------------------------------------------------
__device__ __forceinline__ unsigned f2tf32(float x) {
    unsigned u;
    asm("cvt.rna.tf32.f32 %0, %1;" : "=r"(u) : "f"(x));
    return u;
}

__device__ __forceinline__ void mma_tf32(
    float& c0, float& c1, float& c2, float& c3,
    unsigned a0, unsigned a1, unsigned a2, unsigned a3,
    unsigned b0, unsigned b1)
{
    asm volatile(
        "mma.sync.aligned.m16n8k8.row.col.f32.tf32.tf32.f32 "
        "{%0,%1,%2,%3}, {%4,%5,%6,%7}, {%8,%9}, {%0,%1,%2,%3};"
        : "+f"(c0), "+f"(c1), "+f"(c2), "+f"(c3)
        : "r"(a0), "r"(a1), "r"(a2), "r"(a3), "r"(b0), "r"(b1));
}

__device__ __forceinline__ void cp_async16(void* smem, const void* gmem) {
    unsigned saddr = (unsigned)__cvta_generic_to_shared(smem);
    asm volatile("cp.async.cg.shared.global [%0], [%1], 16;"
                 :: "r"(saddr), "l"(gmem));
}

// ---------------------------------------------------------------------------
// Tensor-core tf32 GEMM: C[M,N] = A[M,K] @ B[K,N], row-major.
// 128x128 tile, BK=16, 8 warps x (32x64), cp.async 2-stage double buffer.
// M,N multiples of 128; K multiple of 16.
// ---------------------------------------------------------------------------
#define AS_STR 20    // A smem stride (floats): 20g+t bijective mod 32
#define BS_STR 136   // B smem stride (floats): 136%32=8 -> 8t+g bijective

__global__ void __launch_bounds__(256) tgemm_kernel(
    const float* __restrict__ A, const float* __restrict__ B,
    float* __restrict__ C, int M, int N, int K)
{
    __shared__ float As[2][128][AS_STR];
    __shared__ float Bs[2][16][BS_STR];

    const int tid  = threadIdx.x;
    const int w    = tid >> 5;
    const int lane = tid & 31;
    const int g    = lane >> 2;      // 0..7
    const int t    = lane & 3;       // 0..3
    const int wm   = (w & 3) * 32;   // warp m-offset in tile
    const int wn   = (w >> 2) * 64;  // warp n-offset in tile

    const int mbase = blockIdx.y * 128;
    const int nbase = blockIdx.x * 128;

    // Loader mappings (512 16B-chunks per tile each for A and B; 2 per thread)
    const int arow0 = tid >> 2,        acc0 = (tid & 3) * 4;          // chunk tid
    const int arow1 = (tid + 256) >> 2, acc1 = ((tid + 256) & 3) * 4; // chunk tid+256
    const int brow0 = tid >> 5,        bcc0 = (tid & 31) * 4;
    const int brow1 = (tid + 256) >> 5, bcc1 = ((tid + 256) & 31) * 4;

    float acc[2][8][4];
#pragma unroll
    for (int mt = 0; mt < 2; mt++)
#pragma unroll
        for (int nt = 0; nt < 8; nt++)
#pragma unroll
            for (int j = 0; j < 4; j++) acc[mt][nt][j] = 0.f;

    const int NIT = K / 16;

    // Prefetch tile 0
    {
        const int k0 = 0;
        cp_async16(&As[0][arow0][acc0], A + (size_t)(mbase + arow0) * K + k0 + acc0);
        cp_async16(&As[0][arow1][acc1], A + (size_t)(mbase + arow1) * K + k0 + acc1);
        cp_async16(&Bs[0][brow0][bcc0], B + (size_t)(k0 + brow0) * N + nbase + bcc0);
        cp_async16(&Bs[0][brow1][bcc1], B + (size_t)(k0 + brow1) * N + nbase + bcc1);
        asm volatile("cp.async.commit_group;");
    }

    for (int it = 0; it < NIT; it++) {
        const int buf = it & 1;
        if (it + 1 < NIT) {
            const int k0 = (it + 1) * 16;
            const int nb = buf ^ 1;
            cp_async16(&As[nb][arow0][acc0], A + (size_t)(mbase + arow0) * K + k0 + acc0);
            cp_async16(&As[nb][arow1][acc1], A + (size_t)(mbase + arow1) * K + k0 + acc1);
            cp_async16(&Bs[nb][brow0][bcc0], B + (size_t)(k0 + brow0) * N + nbase + bcc0);
            cp_async16(&Bs[nb][brow1][bcc1], B + (size_t)(k0 + brow1) * N + nbase + bcc1);
            asm volatile("cp.async.commit_group;");
            asm volatile("cp.async.wait_group 1;");
        } else {
            asm volatile("cp.async.wait_group 0;");
        }
        __syncthreads();

#pragma unroll
        for (int kc = 0; kc < 2; kc++) {
            unsigned af[2][4];
#pragma unroll
            for (int mt = 0; mt < 2; mt++) {
                const int m = wm + mt * 16;
                af[mt][0] = f2tf32(As[buf][m + g][kc * 8 + t]);
                af[mt][1] = f2tf32(As[buf][m + 8 + g][kc * 8 + t]);
                af[mt][2] = f2tf32(As[buf][m + g][kc * 8 + t + 4]);
                af[mt][3] = f2tf32(As[buf][m + 8 + g][kc * 8 + t + 4]);
            }
#pragma unroll
            for (int nt = 0; nt < 8; nt++) {
                unsigned b0 = f2tf32(Bs[buf][kc * 8 + t][wn + nt * 8 + g]);
                unsigned b1 = f2tf32(Bs[buf][kc * 8 + t + 4][wn + nt * 8 + g]);
                mma_tf32(acc[0][nt][0], acc[0][nt][1], acc[0][nt][2], acc[0][nt][3],
                         af[0][0], af[0][1], af[0][2], af[0][3], b0, b1);
                mma_tf32(acc[1][nt][0], acc[1][nt][1], acc[1][nt][2], acc[1][nt][3],
                         af[1][0], af[1][1], af[1][2], af[1][3], b0, b1);
            }
        }
        __syncthreads();
    }

    // Epilogue
#pragma unroll
    for (int mt = 0; mt < 2; mt++) {
        const int r0 = mbase + wm + mt * 16 + g;
#pragma unroll
        for (int nt = 0; nt < 8; nt++) {
            const int col = nbase + wn + nt * 8 + 2 * t;
            *(float2*)(C + (size_t)r0 * N + col) =
                make_float2(acc[mt][nt][0], acc[mt][nt][1]);
            *(float2*)(C + (size_t)(r0 + 8) * N + col) =
                make_float2(acc[mt][nt][2], acc[mt][nt][3]);
        }
    }
}

// ---------------------------------------------------------------------------
// Tensor-core causal flash attention (unchanged from R2).
// Block = 128 threads (4 warps), 64 q-rows per block; warp w owns rows
// [w*16, w*16+16). qk: [b*n, 2048], q at col h*64, k at col 1024+h*64.
// ---------------------------------------------------------------------------
__global__ void __launch_bounds__(128) attn_tc_kernel(
    const float* __restrict__ qk, float* __restrict__ out)
{
    const int qt = blockIdx.x, h = blockIdx.y, bb = blockIdx.z;
    const int tid  = threadIdx.x;
    const int w    = tid >> 5;
    const int lane = tid & 31;
    const int g    = lane >> 2;
    const int t    = lane & 3;

    __shared__ float Ks[64][68];

    const int qrow0 = bb * N_TOK + qt * 64 + w * 16;
    unsigned qf[8][4];
#pragma unroll
    for (int kc = 0; kc < 8; kc++) {
        const float* qp  = qk + (size_t)(qrow0 + g) * (2 * DIMM) + h * DHEAD + kc * 8;
        const float* qp8 = qp + (size_t)8 * (2 * DIMM);
        qf[kc][0] = f2tf32(qp[t]      * BETA_V);
        qf[kc][1] = f2tf32(qp8[t]     * BETA_V);
        qf[kc][2] = f2tf32(qp[t + 4]  * BETA_V);
        qf[kc][3] = f2tf32(qp8[t + 4] * BETA_V);
    }

    float o[8][4];
#pragma unroll
    for (int nt = 0; nt < 8; nt++)
#pragma unroll
        for (int j = 0; j < 4; j++) o[nt][j] = 0.f;
    float m0 = -1e30f, m1 = -1e30f, l0 = 0.f, l1 = 0.f;

    for (int kt = 0; kt <= qt; kt++) {
#pragma unroll
        for (int i = tid; i < 64 * 16; i += 128) {
            int r = i >> 4, c = (i & 15) * 4;
            const float4 v = *(const float4*)(
                qk + (size_t)(bb * N_TOK + kt * 64 + r) * (2 * DIMM)
                   + DIMM + h * DHEAD + c);
            float4 o4;
            o4.x = __uint_as_float(f2tf32(v.x));
            o4.y = __uint_as_float(f2tf32(v.y));
            o4.z = __uint_as_float(f2tf32(v.z));
            o4.w = __uint_as_float(f2tf32(v.w));
            *(float4*)&Ks[r][c] = o4;
        }
        __syncthreads();

        float sc[8][4];
#pragma unroll
        for (int nt = 0; nt < 8; nt++) {
            sc[nt][0] = sc[nt][1] = sc[nt][2] = sc[nt][3] = 0.f;
#pragma unroll
            for (int kc = 0; kc < 8; kc++) {
                unsigned b0 = __float_as_uint(Ks[nt * 8 + g][kc * 8 + t]);
                unsigned b1 = __float_as_uint(Ks[nt * 8 + g][kc * 8 + t + 4]);
                mma_tf32(sc[nt][0], sc[nt][1], sc[nt][2], sc[nt][3],
                         qf[kc][0], qf[kc][1], qf[kc][2], qf[kc][3], b0, b1);
            }
        }

        if (kt == qt) {
            const int r0 = w * 16 + g, r1 = r0 + 8;
#pragma unroll
            for (int nt = 0; nt < 8; nt++) {
                int col = nt * 8 + 2 * t;
                if (col     > r0) sc[nt][0] = -1e30f;
                if (col + 1 > r0) sc[nt][1] = -1e30f;
                if (col     > r1) sc[nt][2] = -1e30f;
                if (col + 1 > r1) sc[nt][3] = -1e30f;
            }
        }

        float tmax0 = -1e30f, tmax1 = -1e30f;
#pragma unroll
        for (int nt = 0; nt < 8; nt++) {
            tmax0 = fmaxf(tmax0, fmaxf(sc[nt][0], sc[nt][1]));
            tmax1 = fmaxf(tmax1, fmaxf(sc[nt][2], sc[nt][3]));
        }
        tmax0 = fmaxf(tmax0, __shfl_xor_sync(0xffffffffu, tmax0, 1));
        tmax0 = fmaxf(tmax0, __shfl_xor_sync(0xffffffffu, tmax0, 2));
        tmax1 = fmaxf(tmax1, __shfl_xor_sync(0xffffffffu, tmax1, 1));
        tmax1 = fmaxf(tmax1, __shfl_xor_sync(0xffffffffu, tmax1, 2));

        float mn0 = fmaxf(m0, tmax0), mn1 = fmaxf(m1, tmax1);
        float corr0 = __expf(m0 - mn0), corr1 = __expf(m1 - mn1);
        m0 = mn0; m1 = mn1;

        float ls0 = 0.f, ls1 = 0.f;
        unsigned pu[8][4];
#pragma unroll
        for (int nt = 0; nt < 8; nt++) {
            float p0 = __expf(sc[nt][0] - mn0);
            float p1 = __expf(sc[nt][1] - mn0);
            float p2 = __expf(sc[nt][2] - mn1);
            float p3 = __expf(sc[nt][3] - mn1);
            ls0 += p0 + p1;
            ls1 += p2 + p3;
            pu[nt][0] = f2tf32(p0);
            pu[nt][1] = f2tf32(p1);
            pu[nt][2] = f2tf32(p2);
            pu[nt][3] = f2tf32(p3);
        }
        ls0 += __shfl_xor_sync(0xffffffffu, ls0, 1);
        ls0 += __shfl_xor_sync(0xffffffffu, ls0, 2);
        ls1 += __shfl_xor_sync(0xffffffffu, ls1, 1);
        ls1 += __shfl_xor_sync(0xffffffffu, ls1, 2);
        l0 = l0 * corr0 + ls0;
        l1 = l1 * corr1 + ls1;

#pragma unroll
        for (int nt = 0; nt < 8; nt++) {
            o[nt][0] *= corr0; o[nt][1] *= corr0;
            o[nt][2] *= corr1; o[nt][3] *= corr1;
        }

#pragma unroll
        for (int kc = 0; kc < 8; kc++) {
            int src0 = (lane & 28) | (t >> 1);
            int src1 = src0 + 2;
            unsigned v00 = __shfl_sync(0xffffffffu, pu[kc][0], src0);
            unsigned v01 = __shfl_sync(0xffffffffu, pu[kc][1], src0);
            unsigned v10 = __shfl_sync(0xffffffffu, pu[kc][2], src0);
            unsigned v11 = __shfl_sync(0xffffffffu, pu[kc][3], src0);
            unsigned v20 = __shfl_sync(0xffffffffu, pu[kc][0], src1);
            unsigned v21 = __shfl_sync(0xffffffffu, pu[kc][1], src1);
            unsigned v30 = __shfl_sync(0xffffffffu, pu[kc][2], src1);
            unsigned v31 = __shfl_sync(0xffffffffu, pu[kc][3], src1);
            bool odd = (t & 1);
            unsigned a0 = odd ? v01 : v00;
            unsigned a1 = odd ? v11 : v10;
            unsigned a2 = odd ? v21 : v20;
            unsigned a3 = odd ? v31 : v30;

#pragma unroll
            for (int nt = 0; nt < 8; nt++) {
                unsigned b0 = __float_as_uint(Ks[kc * 8 + t][nt * 8 + g]);
                unsigned b1 = __float_as_uint(Ks[kc * 8 + t + 4][nt * 8 + g]);
                mma_tf32(o[nt][0], o[nt][1], o[nt][2], o[nt][3],
                         a0, a1, a2, a3, b0, b1);
            }
        }
        __syncthreads();
    }

    const float inv0 = 1.f / l0, inv1 = 1.f / l1;
    float* op0 = out + (size_t)(qrow0 + g) * DIMM + h * DHEAD;
    float* op1 = op0 + (size_t)8 * DIMM;
#pragma unroll
    for (int nt = 0; nt < 8; nt++) {
        *(float2*)(op0 + nt * 8 + 2 * t) =
            make_float2(o[nt][0] * inv0, o[nt][1] * inv0);
        *(float2*)(op1 + nt * 8 + 2 * t) =
            make_float2(o[nt][2] * inv1, o[nt][3] * inv1);
    }
}

// ---------------------------------------------------------------------------
extern "C" void kernel_launch(void* const* d_in, const int* in_sizes, int n_in,
                              void* d_out, int out_size)
{
    const float* x     = (const float*)d_in[0];
    const float* W_qk  = (const float*)d_in[1];
    const float* W_out = (const float*)d_in[2];
    float* out = (float*)d_out;

    float *qkbuf = nullptr, *aobuf = nullptr;
    cudaGetSymbolAddress((void**)&qkbuf, g_qk);
    cudaGetSymbolAddress((void**)&aobuf, g_ao);

    // qk = x @ W_qk : [4096,1024]@[1024,2048]
    tgemm_kernel<<<dim3((2 * DIMM) / 128, (NBATCH * N_TOK) / 128), 256>>>(
        x, W_qk, qkbuf, NBATCH * N_TOK, 2 * DIMM, DIMM);
    // causal attention (tf32 tensor cores), K reused as V
    attn_tc_kernel<<<dim3(N_TOK / 64, NHEAD, NBATCH), 128>>>(qkbuf, aobuf);
    // out = ao @ W_out : [4096,1024]@[1024,1024]
    tgemm_kernel<<<dim3(DIMM / 128, (NBATCH * N_TOK) / 128), 256>>>(
        aobuf, W_out, out, NBATCH * N_TOK, DIMM, DIMM);
}